// round 11
// baseline (speedup 1.0000x reference)
#include <cuda_runtime.h>

// TERMINAL KERNEL — HBM-roofline-bound.
// Measured ceiling ~6.5 TB/s (82% of spec) for this irreducible
// 256MB-read + 256MB-write stream; DRAM pipe pinned at 78-82% across five
// structurally distinct geometries (MLP 1/4/8, consecutive vs block-strided,
// 128/256 threads, cache hints on/off). Remaining gap to spec is DRAM
// read/write turnaround + refresh, not kernel-addressable (LTS cap is
// path-independent on B300: LDG.cv == TMA).
//
//  - 4x block-strided rows/thread: every LDG/STG.128 warp-coalesced
//    (contiguous 512B per instruction), 4 independent front-batched loads
//    (MLP_p1=4, the measured optimum vs 1 and 8).
//  - __ldcs/__stcs: evict-first; zero-reuse stream keeps L2 clean.
//  - Half-angle identity: cos^2(t/2) = 0.5 + 0.5*cos(t),
//    sin^2(t/2) = 0.5 - 0.5*cos(t) -> one MUFU per row, short dep chain,
//    exact complement (s2 + c2 = 1). rel_err 1.45e-7.
__global__ void __launch_bounds__(256)
quantum_probs_final(const float4* __restrict__ in,
                    float4* __restrict__ out,
                    int n) {
    const int tid = threadIdx.x;
    const int stride = blockDim.x;
    const int base = blockIdx.x * (stride * 4) + tid;

    if (base + 3 * stride < n) {
        float4 r0 = __ldcs(&in[base + 0 * stride]);
        float4 r1 = __ldcs(&in[base + 1 * stride]);
        float4 r2 = __ldcs(&in[base + 2 * stride]);
        float4 r3 = __ldcs(&in[base + 3 * stride]);

        float t0 = __cosf(r0.x);
        float t1 = __cosf(r1.x);
        float t2 = __cosf(r2.x);
        float t3 = __cosf(r3.x);

        float c20 = fmaf(0.5f, t0, 0.5f), s20 = fmaf(-0.5f, t0, 0.5f);
        float c21 = fmaf(0.5f, t1, 0.5f), s21 = fmaf(-0.5f, t1, 0.5f);
        float c22 = fmaf(0.5f, t2, 0.5f), s22 = fmaf(-0.5f, t2, 0.5f);
        float c23 = fmaf(0.5f, t3, 0.5f), s23 = fmaf(-0.5f, t3, 0.5f);

        __stcs(&out[base + 0 * stride], make_float4(c20 * c20, c20 * s20, s20 * s20, s20 * c20));
        __stcs(&out[base + 1 * stride], make_float4(c21 * c21, c21 * s21, s21 * s21, s21 * c21));
        __stcs(&out[base + 2 * stride], make_float4(c22 * c22, c22 * s22, s22 * s22, s22 * c22));
        __stcs(&out[base + 3 * stride], make_float4(c23 * c23, c23 * s23, s23 * s23, s23 * c23));
    } else {
        // Tail path (not taken for N = 16M: 1024 rows/block divides N)
        for (int i = base; i < n; i += stride) {
            float4 rr = __ldcs(&in[i]);
            float t = __cosf(rr.x);
            float c2 = fmaf(0.5f, t, 0.5f);
            float s2 = fmaf(-0.5f, t, 0.5f);
            __stcs(&out[i], make_float4(c2 * c2, c2 * s2, s2 * s2, s2 * c2));
        }
    }
}

extern "C" void kernel_launch(void* const* d_in, const int* in_sizes, int n_in,
                              void* d_out, int out_size) {
    const float4* in = (const float4*)d_in[0];
    float4* out = (float4*)d_out;
    int n = in_sizes[0] / 4;                  // N rows
    int threads = 256;
    int rows_per_block = threads * 4;
    int blocks = (n + rows_per_block - 1) / rows_per_block;
    quantum_probs_final<<<blocks, threads>>>(in, out, n);
}

// round 12
// speedup vs baseline: 1.0105x; 1.0105x over previous
#include <cuda_runtime.h>

// TERMINAL KERNEL — HBM-roofline-bound. (Held from R9; R10 re-run established
// the ±1us run-to-run noise band, and all geometries since R3 sit inside it.)
//
// Ceiling: ~6.4-6.5 TB/s (80-82% of 8 TB/s spec) for this irreducible
// interleaved 256MB-read + 256MB-write stream. Traffic is provably minimal:
// col-0 values at 16B pitch touch every 32B input sector; output fully
// written with full-sector STG.128. Gap to spec = DRAM r/w turnaround +
// refresh. LTS cap is path-independent (LDG.cv == TMA) -> no access-path
// rewrite can move it. Compute pipes <5% busy.
//
//  - 4x block-strided rows/thread: every LDG/STG.128 warp-coalesced
//    (contiguous 512B per instruction), 4 independent front-batched loads
//    (MLP_p1=4, measured optimum vs 1 and 8).
//  - __ldcs/__stcs: evict-first; zero-reuse stream keeps L2 clean.
//  - Half-angle identity: cos^2(t/2) = 0.5 + 0.5*cos(t),
//    sin^2(t/2) = 0.5 - 0.5*cos(t) -> one MUFU per row, short dep chain,
//    exact complement (s2 + c2 = 1). rel_err 1.45e-7.
__global__ void __launch_bounds__(256)
quantum_probs_final(const float4* __restrict__ in,
                    float4* __restrict__ out,
                    int n) {
    const int tid = threadIdx.x;
    const int stride = blockDim.x;
    const int base = blockIdx.x * (stride * 4) + tid;

    if (base + 3 * stride < n) {
        float4 r0 = __ldcs(&in[base + 0 * stride]);
        float4 r1 = __ldcs(&in[base + 1 * stride]);
        float4 r2 = __ldcs(&in[base + 2 * stride]);
        float4 r3 = __ldcs(&in[base + 3 * stride]);

        float t0 = __cosf(r0.x);
        float t1 = __cosf(r1.x);
        float t2 = __cosf(r2.x);
        float t3 = __cosf(r3.x);

        float c20 = fmaf(0.5f, t0, 0.5f), s20 = fmaf(-0.5f, t0, 0.5f);
        float c21 = fmaf(0.5f, t1, 0.5f), s21 = fmaf(-0.5f, t1, 0.5f);
        float c22 = fmaf(0.5f, t2, 0.5f), s22 = fmaf(-0.5f, t2, 0.5f);
        float c23 = fmaf(0.5f, t3, 0.5f), s23 = fmaf(-0.5f, t3, 0.5f);

        __stcs(&out[base + 0 * stride], make_float4(c20 * c20, c20 * s20, s20 * s20, s20 * c20));
        __stcs(&out[base + 1 * stride], make_float4(c21 * c21, c21 * s21, s21 * s21, s21 * c21));
        __stcs(&out[base + 2 * stride], make_float4(c22 * c22, c22 * s22, s22 * s22, s22 * c22));
        __stcs(&out[base + 3 * stride], make_float4(c23 * c23, c23 * s23, s23 * s23, s23 * c23));
    } else {
        // Tail path (not taken for N = 16M: 1024 rows/block divides N)
        for (int i = base; i < n; i += stride) {
            float4 rr = __ldcs(&in[i]);
            float t = __cosf(rr.x);
            float c2 = fmaf(0.5f, t, 0.5f);
            float s2 = fmaf(-0.5f, t, 0.5f);
            __stcs(&out[i], make_float4(c2 * c2, c2 * s2, s2 * s2, s2 * c2));
        }
    }
}

extern "C" void kernel_launch(void* const* d_in, const int* in_sizes, int n_in,
                              void* d_out, int out_size) {
    const float4* in = (const float4*)d_in[0];
    float4* out = (float4*)d_out;
    int n = in_sizes[0] / 4;                  // N rows
    int threads = 256;
    int rows_per_block = threads * 4;
    int blocks = (n + rows_per_block - 1) / rows_per_block;
    quantum_probs_final<<<blocks, threads>>>(in, out, n);
}